// round 1
// baseline (speedup 1.0000x reference)
#include <cuda_runtime.h>
#include <math.h>

#define NIMG     1024
#define CIN      3
#define HH       32
#define WWID     32
#define OF       64
#define KPATCH   27
#define THREADS  256
#define XS_PITCH 36   // padded row pitch (34 used)

#define SELU_SCALE   1.0507009873554805f
#define SELU_AS      1.7580993408473766f   // scale * alpha

__device__ __forceinline__ unsigned long long pack2(float a, float b) {
    unsigned long long r;
    asm("mov.b64 %0, {%1, %2};" : "=l"(r) : "f"(a), "f"(b));
    return r;
}
__device__ __forceinline__ void unpack2(unsigned long long v, float& a, float& b) {
    asm("mov.b64 {%0, %1}, %2;" : "=f"(a), "=f"(b) : "l"(v));
}
// Blackwell packed dual-FMA: 2x fp32 FMA throughput vs scalar FFMA.
__device__ __forceinline__ void fma2(unsigned long long& acc, unsigned long long x, unsigned long long w) {
    asm("fma.rn.f32x2 %0, %1, %2, %0;" : "+l"(acc) : "l"(x), "l"(w));
}

__device__ __forceinline__ float selu_f(float v) {
    return v > 0.0f ? SELU_SCALE * v : SELU_AS * expm1f(v);
}

__global__ void __launch_bounds__(THREADS) fused_conv_selu_pool_gate(
    const float* __restrict__ x,      // (1024, 3, 32, 32)
    const float* __restrict__ wgt,    // (27, 64)
    const float* __restrict__ bias,   // (64)
    const float* __restrict__ sproj,  // (3, 64)
    const float* __restrict__ sbias,  // (64)
    float* __restrict__ out)          // (1024, 64)
{
    __shared__ float xs[CIN][34][XS_PITCH];     // image w/ halo
    __shared__ float wsd[KPATCH][2 * OF];       // weights, each duplicated {w,w}
    __shared__ float bsd[2 * OF];               // bias duplicated
    __shared__ float gsh[OF];                   // gate
    __shared__ float red[8][16];                // cross-warp reduction
    __shared__ float csum_sh[8][CIN];           // per-warp channel sums

    const int n    = blockIdx.x;
    const int tid  = threadIdx.x;
    const int lane = tid & 31;
    const int warp = tid >> 5;
    const float* xn = x + (size_t)n * (CIN * HH * WWID);

    // ---- stage weights (duplicated for f32x2) ----
    for (int i = tid; i < KPATCH * OF; i += THREADS) {
        float v = wgt[i];
        int k = i >> 6, o = i & 63;
        wsd[k][2 * o]     = v;
        wsd[k][2 * o + 1] = v;
    }
    if (tid < OF) {
        float v = bias[tid];
        bsd[2 * tid]     = v;
        bsd[2 * tid + 1] = v;
    }

    // ---- stage image with zero halo; accumulate channel sums on the fly ----
    float cs0 = 0.f, cs1 = 0.f, cs2 = 0.f;
    for (int i = tid; i < CIN * 34 * 34; i += THREADS) {
        int c  = i / (34 * 34);
        int r  = i % (34 * 34);
        int hh = r / 34, ww = r % 34;
        float v = 0.f;
        if (hh >= 1 && hh <= 32 && ww >= 1 && ww <= 32) {
            v = xn[c * (HH * WWID) + (hh - 1) * WWID + (ww - 1)];
            if (c == 0)      cs0 += v;
            else if (c == 1) cs1 += v;
            else             cs2 += v;
        }
        xs[c][hh][ww] = v;
    }
    #pragma unroll
    for (int off = 16; off; off >>= 1) {
        cs0 += __shfl_xor_sync(0xffffffffu, cs0, off);
        cs1 += __shfl_xor_sync(0xffffffffu, cs1, off);
        cs2 += __shfl_xor_sync(0xffffffffu, cs2, off);
    }
    if (lane == 0) {
        csum_sh[warp][0] = cs0;
        csum_sh[warp][1] = cs1;
        csum_sh[warp][2] = cs2;
    }
    __syncthreads();

    // ---- gate: sigmoid(mean(x) @ scale_proj + scale_bias) ----
    if (tid < OF) {
        float s0 = 0.f, s1 = 0.f, s2 = 0.f;
        #pragma unroll
        for (int wz = 0; wz < 8; wz++) {
            s0 += csum_sh[wz][0];
            s1 += csum_sh[wz][1];
            s2 += csum_sh[wz][2];
        }
        const float inv = 1.0f / (HH * WWID);
        float z = s0 * inv * sproj[0 * OF + tid]
                + s1 * inv * sproj[1 * OF + tid]
                + s2 * inv * sproj[2 * OF + tid]
                + sbias[tid];
        gsh[tid] = 1.0f / (1.0f + expf(-z));
    }
    __syncthreads();

    // ---- main: conv + SELU + L2-pool(pairs along W) + spatial sum ----
    // 512 pool-pairs per image; each thread owns 2 pairs. Channels in 4 groups of 16.
    #pragma unroll 1
    for (int cg = 0; cg < 4; cg++) {
        const int o0 = cg << 4;
        float part[16];
        #pragma unroll
        for (int i = 0; i < 16; i++) part[i] = 0.f;

        #pragma unroll
        for (int pp = 0; pp < 2; pp++) {
            const int p  = tid + (pp << 8);
            const int h  = p >> 4;
            const int w0 = (p & 15) << 1;

            unsigned long long acc[16];
            #pragma unroll
            for (int i = 0; i < 16; i++)
                acc[i] = *(const unsigned long long*)&bsd[2 * (o0 + i)];

            #pragma unroll
            for (int c = 0; c < 3; c++) {
                #pragma unroll
                for (int dy = 0; dy < 3; dy++) {
                    #pragma unroll
                    for (int dx = 0; dx < 3; dx++) {
                        const int k = c * 9 + dy * 3 + dx;
                        float xa = xs[c][h + dy][w0 + dx];
                        float xb = xs[c][h + dy][w0 + dx + 1];
                        unsigned long long x2 = pack2(xa, xb);
                        const ulonglong2* wq = (const ulonglong2*)&wsd[k][2 * o0];
                        #pragma unroll
                        for (int i = 0; i < 8; i++) {
                            ulonglong2 wv = wq[i];   // broadcast LDS.128: two dup-packed weights
                            fma2(acc[2 * i],     x2, wv.x);
                            fma2(acc[2 * i + 1], x2, wv.y);
                        }
                    }
                }
            }
            #pragma unroll
            for (int i = 0; i < 16; i++) {
                float a, b;
                unpack2(acc[i], a, b);
                float sa = selu_f(a);
                float sb = selu_f(b);
                part[i] += sqrtf(sa * sa + sb * sb);
            }
        }

        // deterministic block reduction of part[16]
        #pragma unroll
        for (int i = 0; i < 16; i++) {
            float v = part[i];
            v += __shfl_xor_sync(0xffffffffu, v, 16);
            v += __shfl_xor_sync(0xffffffffu, v, 8);
            v += __shfl_xor_sync(0xffffffffu, v, 4);
            v += __shfl_xor_sync(0xffffffffu, v, 2);
            v += __shfl_xor_sync(0xffffffffu, v, 1);
            if (lane == 0) red[warp][i] = v;
        }
        __syncthreads();
        if (tid < 16) {
            float s = 0.f;
            #pragma unroll
            for (int wz = 0; wz < 8; wz++) s += red[wz][tid];
            const int o = o0 + tid;
            out[n * OF + o] = s * (1.0f / 512.0f) * gsh[o];
        }
        __syncthreads();
    }
}

extern "C" void kernel_launch(void* const* d_in, const int* in_sizes, int n_in,
                              void* d_out, int out_size) {
    const float* x      = (const float*)d_in[0];
    const float* weight = (const float*)d_in[1];
    const float* bias   = (const float*)d_in[2];
    const float* sproj  = (const float*)d_in[3];
    const float* sbias  = (const float*)d_in[4];
    float* out = (float*)d_out;
    fused_conv_selu_pool_gate<<<NIMG, THREADS>>>(x, weight, bias, sproj, sbias, out);
}

// round 2
// speedup vs baseline: 5.5091x; 5.5091x over previous
#include <cuda_runtime.h>
#include <math.h>

#define NIMG     1024
#define CIN      3
#define HH       32
#define WWID     32
#define OF       64
#define KPATCH   27
#define THREADS  256
#define XS_PITCH 36   // padded row pitch (34 used)

#define SELU_SCALE   1.0507009873554805f
#define SELU_AS      1.7580993408473766f   // scale * alpha

typedef unsigned long long u64;

__device__ __forceinline__ u64 pack2(float a, float b) {
    u64 r;
    asm("mov.b64 %0, {%1, %2};" : "=l"(r) : "f"(a), "f"(b));
    return r;
}
__device__ __forceinline__ void unpack2(u64 v, float& a, float& b) {
    asm("mov.b64 {%0, %1}, %2;" : "=f"(a), "=f"(b) : "l"(v));
}
// Blackwell packed dual-FMA: 2 fp32 FMAs per instruction.
__device__ __forceinline__ void fma2(u64& acc, u64 x, u64 w) {
    asm("fma.rn.f32x2 %0, %1, %2, %0;" : "+l"(acc) : "l"(x), "l"(w));
}

__device__ __forceinline__ float selu_f(float v) {
    return v > 0.0f ? SELU_SCALE * v : SELU_AS * expm1f(v);
}

__global__ void __launch_bounds__(THREADS, 2) fused_conv_selu_pool_gate(
    const float* __restrict__ x,      // (1024, 3, 32, 32)
    const float* __restrict__ wgt,    // (27, 64)
    const float* __restrict__ bias,   // (64)
    const float* __restrict__ sproj,  // (3, 64)
    const float* __restrict__ sbias,  // (64)
    float* __restrict__ out)          // (1024, 64)
{
    __shared__ __align__(16) float xs[CIN][34][XS_PITCH]; // image w/ halo
    __shared__ __align__(16) float wsd[KPATCH][2 * OF];   // weights dup-packed {w,w}
    __shared__ __align__(16) float bsd[2 * OF];           // bias dup-packed
    __shared__ float gsh[OF];                             // gate
    __shared__ float red[8][16];                          // cross-warp reduction
    __shared__ float csum_sh[8][CIN];                     // per-warp channel sums

    const int n    = blockIdx.x;
    const int tid  = threadIdx.x;
    const int lane = tid & 31;
    const int warp = tid >> 5;
    const float* xn = x + (size_t)n * (CIN * HH * WWID);

    // ---- stage weights (duplicated for f32x2) ----
    for (int i = tid; i < KPATCH * OF; i += THREADS) {
        float v = wgt[i];
        int k = i >> 6, o = i & 63;
        wsd[k][2 * o]     = v;
        wsd[k][2 * o + 1] = v;
    }
    if (tid < OF) {
        float v = bias[tid];
        bsd[2 * tid]     = v;
        bsd[2 * tid + 1] = v;
    }

    // ---- stage image with zero halo; channel sums on the fly ----
    float cs0 = 0.f, cs1 = 0.f, cs2 = 0.f;
    for (int i = tid; i < CIN * 34 * 34; i += THREADS) {
        int c  = i / (34 * 34);
        int r  = i % (34 * 34);
        int hh = r / 34, ww = r % 34;
        float v = 0.f;
        if (hh >= 1 && hh <= 32 && ww >= 1 && ww <= 32) {
            v = xn[c * (HH * WWID) + (hh - 1) * WWID + (ww - 1)];
            if (c == 0)      cs0 += v;
            else if (c == 1) cs1 += v;
            else             cs2 += v;
        }
        xs[c][hh][ww] = v;
    }
    #pragma unroll
    for (int off = 16; off; off >>= 1) {
        cs0 += __shfl_xor_sync(0xffffffffu, cs0, off);
        cs1 += __shfl_xor_sync(0xffffffffu, cs1, off);
        cs2 += __shfl_xor_sync(0xffffffffu, cs2, off);
    }
    if (lane == 0) {
        csum_sh[warp][0] = cs0;
        csum_sh[warp][1] = cs1;
        csum_sh[warp][2] = cs2;
    }
    __syncthreads();

    // ---- gate: sigmoid(mean(x) @ scale_proj + scale_bias) ----
    if (tid < OF) {
        float s0 = 0.f, s1 = 0.f, s2 = 0.f;
        #pragma unroll
        for (int wz = 0; wz < 8; wz++) {
            s0 += csum_sh[wz][0];
            s1 += csum_sh[wz][1];
            s2 += csum_sh[wz][2];
        }
        const float inv = 1.0f / (HH * WWID);
        float z = s0 * inv * sproj[0 * OF + tid]
                + s1 * inv * sproj[1 * OF + tid]
                + s2 * inv * sproj[2 * OF + tid]
                + sbias[tid];
        gsh[tid] = 1.0f / (1.0f + expf(-z));
    }
    __syncthreads();

    const ulonglong2* __restrict__ wall = (const ulonglong2*)wsd;   // row = 32 ulonglong2
    const ulonglong2* __restrict__ ball = (const ulonglong2*)bsd;

    // ---- main: conv + SELU + L2-pool(pairs along W) + spatial sum ----
    // 512 pool-pairs per image; each thread owns 2 pairs. 4 channel groups of 16.
    #pragma unroll 1
    for (int cg = 0; cg < 4; cg++) {
        float part[16];
        #pragma unroll
        for (int i = 0; i < 16; i++) part[i] = 0.f;

        #pragma unroll 1
        for (int pp = 0; pp < 2; pp++) {
            const int p  = tid + (pp << 8);
            const int h  = p >> 4;
            const int w0 = (p & 15) << 1;

            u64 acc[16];
            #pragma unroll
            for (int i = 0; i < 8; i++) {
                ulonglong2 b2 = ball[cg * 8 + i];
                acc[2 * i]     = b2.x;
                acc[2 * i + 1] = b2.y;
            }

            #pragma unroll 1
            for (int cd = 0; cd < 9; cd++) {          // cd = c*3 + dy, rolled
                const int c  = cd / 3;
                const int dy = cd - 3 * c;
                const float* row = &xs[c][h + dy][w0];
                float2 fa = *(const float2*)(row);        // v0 v1 (8B aligned: w0 even)
                float2 fb = *(const float2*)(row + 2);    // v2 v3
                u64 xp[3];
                xp[0] = pack2(fa.x, fa.y);
                xp[1] = pack2(fa.y, fb.x);
                xp[2] = pack2(fb.x, fb.y);
                const ulonglong2* wk = wall + (size_t)cd * 96 + cg * 8; // 3 rows of 32
                #pragma unroll
                for (int dx = 0; dx < 3; dx++) {
                    const ulonglong2* wr = wk + dx * 32;
                    #pragma unroll
                    for (int i = 0; i < 8; i++) {
                        ulonglong2 wv = wr[i];   // broadcast LDS.128
                        fma2(acc[2 * i],     xp[dx], wv.x);
                        fma2(acc[2 * i + 1], xp[dx], wv.y);
                    }
                }
            }

            #pragma unroll
            for (int i = 0; i < 16; i++) {
                float a, b;
                unpack2(acc[i], a, b);
                float sa = selu_f(a);
                float sb = selu_f(b);
                part[i] += sqrtf(sa * sa + sb * sb);
            }
        }

        // deterministic block reduction of part[16]
        #pragma unroll
        for (int i = 0; i < 16; i++) {
            float v = part[i];
            v += __shfl_xor_sync(0xffffffffu, v, 16);
            v += __shfl_xor_sync(0xffffffffu, v, 8);
            v += __shfl_xor_sync(0xffffffffu, v, 4);
            v += __shfl_xor_sync(0xffffffffu, v, 2);
            v += __shfl_xor_sync(0xffffffffu, v, 1);
            if (lane == 0) red[warp][i] = v;
        }
        __syncthreads();
        if (tid < 16) {
            float s = 0.f;
            #pragma unroll
            for (int wz = 0; wz < 8; wz++) s += red[wz][tid];
            const int o = (cg << 4) + tid;
            out[n * OF + o] = s * (1.0f / 512.0f) * gsh[o];
        }
        __syncthreads();
    }
}

extern "C" void kernel_launch(void* const* d_in, const int* in_sizes, int n_in,
                              void* d_out, int out_size) {
    const float* x      = (const float*)d_in[0];
    const float* weight = (const float*)d_in[1];
    const float* bias   = (const float*)d_in[2];
    const float* sproj  = (const float*)d_in[3];
    const float* sbias  = (const float*)d_in[4];
    float* out = (float*)d_out;
    fused_conv_selu_pool_gate<<<NIMG, THREADS>>>(x, weight, bias, sproj, sbias, out);
}

// round 4
// speedup vs baseline: 5.9481x; 1.0797x over previous
#include <cuda_runtime.h>
#include <math.h>

#define NIMG     1024
#define CIN      3
#define HH       32
#define WWID     32
#define OF       64
#define KPATCH   27
#define THREADS  256
#define XS_PITCH 36   // padded row pitch (34 used); 36*4B = 144B, 8B aligned per row

#define SELU_SCALE   1.0507009873554805f
#define SELU_AS      1.7580993408473766f   // scale * alpha

typedef unsigned long long u64;

__device__ __forceinline__ u64 pack2(float a, float b) {
    u64 r;
    asm("mov.b64 %0, {%1, %2};" : "=l"(r) : "f"(a), "f"(b));
    return r;
}
__device__ __forceinline__ void unpack2(u64 v, float& a, float& b) {
    asm("mov.b64 {%0, %1}, %2;" : "=f"(a), "=f"(b) : "l"(v));
}
// Blackwell packed dual-FMA: 2 fp32 FMAs per instruction.
__device__ __forceinline__ void fma2(u64& acc, u64 x, u64 w) {
    asm("fma.rn.f32x2 %0, %1, %2, %0;" : "+l"(acc) : "l"(x), "l"(w));
}

__device__ __forceinline__ float selu_f(float v) {
    return v > 0.0f ? SELU_SCALE * v : SELU_AS * expm1f(v);
}

__global__ void __launch_bounds__(THREADS, 2) fused_conv_selu_pool_gate(
    const float* __restrict__ x,      // (1024, 3, 32, 32)
    const float* __restrict__ wgt,    // (27, 64)
    const float* __restrict__ bias,   // (64)
    const float* __restrict__ sproj,  // (3, 64)
    const float* __restrict__ sbias,  // (64)
    float* __restrict__ out)          // (1024, 64)
{
    __shared__ __align__(16) float xs[CIN][34][XS_PITCH]; // image w/ halo
    __shared__ __align__(16) float wsd[KPATCH][2 * OF];   // weights dup-packed {w,w}
    __shared__ __align__(16) float bsd[2 * OF];           // bias dup-packed
    __shared__ float gsh[OF];                             // gate
    __shared__ float red[8][16];                          // cross-warp reduction
    __shared__ float csum_sh[8][CIN];                     // per-warp channel sums

    const int n    = blockIdx.x;
    const int tid  = threadIdx.x;
    const int lane = tid & 31;
    const int warp = tid >> 5;
    const float* xn = x + (size_t)n * (CIN * HH * WWID);

    // ---- stage weights (duplicated for f32x2) ----
    for (int i = tid; i < KPATCH * OF; i += THREADS) {
        float v = wgt[i];
        int k = i >> 6, o = i & 63;
        wsd[k][2 * o]     = v;
        wsd[k][2 * o + 1] = v;
    }
    if (tid < OF) {
        float v = bias[tid];
        bsd[2 * tid]     = v;
        bsd[2 * tid + 1] = v;
    }

    // ---- stage image with zero halo; channel sums on the fly ----
    float cs0 = 0.f, cs1 = 0.f, cs2 = 0.f;
    for (int i = tid; i < CIN * 34 * 34; i += THREADS) {
        int c  = i / (34 * 34);
        int r  = i % (34 * 34);
        int hh = r / 34, ww = r % 34;
        float v = 0.f;
        if (hh >= 1 && hh <= 32 && ww >= 1 && ww <= 32) {
            v = xn[c * (HH * WWID) + (hh - 1) * WWID + (ww - 1)];
            if (c == 0)      cs0 += v;
            else if (c == 1) cs1 += v;
            else             cs2 += v;
        }
        xs[c][hh][ww] = v;
    }
    #pragma unroll
    for (int off = 16; off; off >>= 1) {
        cs0 += __shfl_xor_sync(0xffffffffu, cs0, off);
        cs1 += __shfl_xor_sync(0xffffffffu, cs1, off);
        cs2 += __shfl_xor_sync(0xffffffffu, cs2, off);
    }
    if (lane == 0) {
        csum_sh[warp][0] = cs0;
        csum_sh[warp][1] = cs1;
        csum_sh[warp][2] = cs2;
    }
    __syncthreads();

    // ---- gate: sigmoid(mean(x) @ scale_proj + scale_bias) ----
    if (tid < OF) {
        float s0 = 0.f, s1 = 0.f, s2 = 0.f;
        #pragma unroll
        for (int wz = 0; wz < 8; wz++) {
            s0 += csum_sh[wz][0];
            s1 += csum_sh[wz][1];
            s2 += csum_sh[wz][2];
        }
        const float inv = 1.0f / (HH * WWID);
        float z = s0 * inv * sproj[0 * OF + tid]
                + s1 * inv * sproj[1 * OF + tid]
                + s2 * inv * sproj[2 * OF + tid]
                + sbias[tid];
        gsh[tid] = 1.0f / (1.0f + expf(-z));
    }
    __syncthreads();

    const ulonglong2* __restrict__ wall = (const ulonglong2*)wsd;   // row = 32 ulonglong2
    const ulonglong2* __restrict__ ball = (const ulonglong2*)bsd;

    // Pair A = tid, pair B = tid + 256 (hB = hA + 16).
    const int hA  = tid >> 4;
    const int w0  = (tid & 15) << 1;
    const float* rowA0 = &xs[0][hA][w0];
    const float* rowB0 = rowA0 + 16 * XS_PITCH;

    // ---- main: conv + SELU + L2-pool(pairs along W) + spatial sum ----
    #pragma unroll 1
    for (int cg = 0; cg < 4; cg++) {
        u64 accA[16], accB[16];
        #pragma unroll
        for (int i = 0; i < 8; i++) {
            ulonglong2 b2 = ball[cg * 8 + i];
            accA[2 * i]     = b2.x;
            accA[2 * i + 1] = b2.y;
            accB[2 * i]     = b2.x;
            accB[2 * i + 1] = b2.y;
        }

        const float* rA = rowA0;
        const float* rB = rowB0;
        const ulonglong2* wk = wall + cg * 8;

        #pragma unroll 1
        for (int c = 0; c < 3; c++) {
            #pragma unroll 1
            for (int dy = 0; dy < 3; dy++) {
                float2 a0 = *(const float2*)(rA);
                float2 a1 = *(const float2*)(rA + 2);
                float2 b0 = *(const float2*)(rB);
                float2 b1 = *(const float2*)(rB + 2);
                u64 xpA[3], xpB[3];
                xpA[0] = pack2(a0.x, a0.y);
                xpA[1] = pack2(a0.y, a1.x);
                xpA[2] = pack2(a1.x, a1.y);
                xpB[0] = pack2(b0.x, b0.y);
                xpB[1] = pack2(b0.y, b1.x);
                xpB[2] = pack2(b1.x, b1.y);
                #pragma unroll
                for (int dx = 0; dx < 3; dx++) {
                    const ulonglong2* wr = wk + dx * 32;
                    #pragma unroll
                    for (int i = 0; i < 8; i++) {
                        ulonglong2 wv = wr[i];   // broadcast LDS.128, feeds 4 FFMA2
                        fma2(accA[2 * i],     xpA[dx], wv.x);
                        fma2(accA[2 * i + 1], xpA[dx], wv.y);
                        fma2(accB[2 * i],     xpB[dx], wv.x);
                        fma2(accB[2 * i + 1], xpB[dx], wv.y);
                    }
                }
                rA += XS_PITCH;
                rB += XS_PITCH;
                wk += 96;                 // next cd: 3 dx-rows of 32 ulonglong2
            }
            rA += (34 - 3) * XS_PITCH;    // advance to next channel (undo 3 dy steps)
            rB += (34 - 3) * XS_PITCH;
        }

        float part[16];
        #pragma unroll
        for (int i = 0; i < 16; i++) {
            float a, b;
            unpack2(accA[i], a, b);
            float sa = selu_f(a);
            float sb = selu_f(b);
            float pA = sqrtf(sa * sa + sb * sb);
            unpack2(accB[i], a, b);
            sa = selu_f(a);
            sb = selu_f(b);
            part[i] = pA + sqrtf(sa * sa + sb * sb);
        }

        // deterministic block reduction of part[16]
        #pragma unroll
        for (int i = 0; i < 16; i++) {
            float v = part[i];
            v += __shfl_xor_sync(0xffffffffu, v, 16);
            v += __shfl_xor_sync(0xffffffffu, v, 8);
            v += __shfl_xor_sync(0xffffffffu, v, 4);
            v += __shfl_xor_sync(0xffffffffu, v, 2);
            v += __shfl_xor_sync(0xffffffffu, v, 1);
            if (lane == 0) red[warp][i] = v;
        }
        __syncthreads();
        if (tid < 16) {
            float s = 0.f;
            #pragma unroll
            for (int wz = 0; wz < 8; wz++) s += red[wz][tid];
            const int o = (cg << 4) + tid;
            out[n * OF + o] = s * (1.0f / 512.0f) * gsh[o];
        }
        __syncthreads();
    }
}

extern "C" void kernel_launch(void* const* d_in, const int* in_sizes, int n_in,
                              void* d_out, int out_size) {
    const float* x      = (const float*)d_in[0];
    const float* weight = (const float*)d_in[1];
    const float* bias   = (const float*)d_in[2];
    const float* sproj  = (const float*)d_in[3];
    const float* sbias  = (const float*)d_in[4];
    float* out = (float*)d_out;
    fused_conv_selu_pool_gate<<<NIMG, THREADS>>>(x, weight, bias, sproj, sbias, out);
}

// round 5
// speedup vs baseline: 9.3471x; 1.5714x over previous
#include <cuda_runtime.h>
#include <math.h>

#define NIMG     1024
#define CIN      3
#define HH       32
#define WWID     32
#define OF       64
#define KPATCH   27
#define THREADS  256
#define XS_PITCH 36   // padded row pitch; 144B rows, 16B-aligned

#define SELU_SCALE   1.0507009873554805f
#define SELU_AS      1.7580993408473766f   // scale * alpha

typedef unsigned long long u64;

__device__ __forceinline__ void unpack2(u64 v, float& a, float& b) {
    asm("mov.b64 {%0, %1}, %2;" : "=f"(a), "=f"(b) : "l"(v));
}
// Blackwell packed dual-FMA: 2 fp32 FMAs per instruction.
__device__ __forceinline__ void fma2(u64& acc, u64 x, u64 w) {
    asm("fma.rn.f32x2 %0, %1, %2, %0;" : "+l"(acc) : "l"(x), "l"(w));
}

// Branchless SELU; negative branch uses MUFU-based __expf (off the fma pipe).
__device__ __forceinline__ float selu_f(float v) {
    float e   = __expf(v);
    float neg = SELU_AS * (e - 1.0f);
    float pos = SELU_SCALE * v;
    return v > 0.0f ? pos : neg;
}

__global__ void __launch_bounds__(THREADS, 3) fused_conv_selu_pool_gate(
    const float* __restrict__ x,      // (1024, 3, 32, 32)
    const float* __restrict__ wgt,    // (27, 64)
    const float* __restrict__ bias,   // (64)
    const float* __restrict__ sproj,  // (3, 64)
    const float* __restrict__ sbias,  // (64)
    float* __restrict__ out)          // (1024, 64)
{
    __shared__ __align__(16) float xs [CIN][34][XS_PITCH]; // image w/ halo
    __shared__ __align__(16) float xsS[CIN][34][XS_PITCH]; // shifted copy: xsS[w] = xs[w+1]
    __shared__ __align__(16) float wsd[KPATCH][2 * OF];    // weights dup-packed {w,w}
    __shared__ __align__(16) float bsd[2 * OF];            // bias dup-packed
    __shared__ float gsh[OF];                              // gate
    __shared__ float red[8][OF];                           // per-warp partials, all 64 ch
    __shared__ float csum_sh[8][CIN];                      // per-warp channel sums

    const int n    = blockIdx.x;
    const int tid  = threadIdx.x;
    const int lane = tid & 31;
    const int warp = tid >> 5;
    const float* xn = x + (size_t)n * (CIN * HH * WWID);

    // ---- stage weights (duplicated for f32x2) ----
    for (int i = tid; i < KPATCH * OF; i += THREADS) {
        float v = wgt[i];
        int k = i >> 6, o = i & 63;
        wsd[k][2 * o]     = v;
        wsd[k][2 * o + 1] = v;
    }
    if (tid < OF) {
        float v = bias[tid];
        bsd[2 * tid]     = v;
        bsd[2 * tid + 1] = v;
    }

    // ---- stage image (plus shifted copy) with zero halo; channel sums on the fly ----
    float cs0 = 0.f, cs1 = 0.f, cs2 = 0.f;
    for (int i = tid; i < CIN * 34 * 34; i += THREADS) {
        int c  = i / (34 * 34);
        int r  = i % (34 * 34);
        int hh = r / 34, ww = r % 34;
        float v = 0.f;
        if (hh >= 1 && hh <= 32 && ww >= 1 && ww <= 32) {
            v = xn[c * (HH * WWID) + (hh - 1) * WWID + (ww - 1)];
            if (c == 0)      cs0 += v;
            else if (c == 1) cs1 += v;
            else             cs2 += v;
        }
        xs[c][hh][ww] = v;
        if (ww >= 1) xsS[c][hh][ww - 1] = v;
    }
    #pragma unroll
    for (int off = 16; off; off >>= 1) {
        cs0 += __shfl_xor_sync(0xffffffffu, cs0, off);
        cs1 += __shfl_xor_sync(0xffffffffu, cs1, off);
        cs2 += __shfl_xor_sync(0xffffffffu, cs2, off);
    }
    if (lane == 0) {
        csum_sh[warp][0] = cs0;
        csum_sh[warp][1] = cs1;
        csum_sh[warp][2] = cs2;
    }
    __syncthreads();

    // ---- gate: sigmoid(mean(x) @ scale_proj + scale_bias) ----
    if (tid < OF) {
        float s0 = 0.f, s1 = 0.f, s2 = 0.f;
        #pragma unroll
        for (int wz = 0; wz < 8; wz++) {
            s0 += csum_sh[wz][0];
            s1 += csum_sh[wz][1];
            s2 += csum_sh[wz][2];
        }
        const float inv = 1.0f / (HH * WWID);
        float z = s0 * inv * sproj[0 * OF + tid]
                + s1 * inv * sproj[1 * OF + tid]
                + s2 * inv * sproj[2 * OF + tid]
                + sbias[tid];
        gsh[tid] = 1.0f / (1.0f + __expf(-z));
    }
    __syncthreads();

    const ulonglong2* __restrict__ wall = (const ulonglong2*)wsd;   // 32 ulonglong2 per k-row
    const ulonglong2* __restrict__ ball = (const ulonglong2*)bsd;   // 32 ulonglong2 total

    // Pair A = tid, pair B = tid + 256 (hB = hA + 16).
    const int hA = tid >> 4;
    const int w0 = (tid & 15) << 1;
    const float* rowA0  = &xs [0][hA][w0];
    const float* rowB0  = rowA0 + 16 * XS_PITCH;
    const float* rowA0s = &xsS[0][hA][w0];
    const float* rowB0s = rowA0s + 16 * XS_PITCH;

    // ---- main: conv + SELU + L2-pool(pairs along W) + spatial sum ----
    // 8 channel groups of 8; acc = 16 u64 -> ~80 regs -> 3 CTAs/SM.
    #pragma unroll 1
    for (int cg = 0; cg < 8; cg++) {
        u64 accA[8], accB[8];
        #pragma unroll
        for (int j = 0; j < 4; j++) {
            ulonglong2 b2 = ball[cg * 4 + j];
            accA[2 * j]     = b2.x;
            accA[2 * j + 1] = b2.y;
            accB[2 * j]     = b2.x;
            accB[2 * j + 1] = b2.y;
        }

        const float* rA  = rowA0;
        const float* rB  = rowB0;
        const float* rAs = rowA0s;
        const float* rBs = rowB0s;
        const ulonglong2* wk = wall + cg * 4;

        #pragma unroll 1
        for (int c = 0; c < 3; c++) {
            #pragma unroll 1
            for (int dy = 0; dy < 3; dy++) {
                // all pixel pairs are direct aligned LDS.64 (no pack MOVs)
                u64 xA0 = *(const u64*)(rA);        // {x[w0],   x[w0+1]}
                u64 xA1 = *(const u64*)(rAs);       // {x[w0+1], x[w0+2]}
                u64 xA2 = *(const u64*)(rA + 2);    // {x[w0+2], x[w0+3]}
                u64 xB0 = *(const u64*)(rB);
                u64 xB1 = *(const u64*)(rBs);
                u64 xB2 = *(const u64*)(rB + 2);

                #pragma unroll
                for (int dx = 0; dx < 3; dx++) {
                    const ulonglong2* wr = wk + dx * 32;
                    u64 xa = dx == 0 ? xA0 : (dx == 1 ? xA1 : xA2);
                    u64 xb = dx == 0 ? xB0 : (dx == 1 ? xB1 : xB2);
                    #pragma unroll
                    for (int j = 0; j < 4; j++) {
                        ulonglong2 wv = wr[j];   // broadcast LDS.128, feeds 4 FFMA2
                        fma2(accA[2 * j],     xa, wv.x);
                        fma2(accA[2 * j + 1], xa, wv.y);
                        fma2(accB[2 * j],     xb, wv.x);
                        fma2(accB[2 * j + 1], xb, wv.y);
                    }
                }
                rA  += XS_PITCH;
                rB  += XS_PITCH;
                rAs += XS_PITCH;
                rBs += XS_PITCH;
                wk  += 96;                 // 3 k-rows of 32 ulonglong2
            }
            rA  += (34 - 3) * XS_PITCH;    // jump to next channel plane
            rB  += (34 - 3) * XS_PITCH;
            rAs += (34 - 3) * XS_PITCH;
            rBs += (34 - 3) * XS_PITCH;
        }

        // SELU + pair-L2 + per-warp reduce (no barrier here)
        #pragma unroll
        for (int i = 0; i < 8; i++) {
            float a, b;
            unpack2(accA[i], a, b);
            float sa = selu_f(a);
            float sb = selu_f(b);
            float v = sqrtf(sa * sa + sb * sb);
            unpack2(accB[i], a, b);
            sa = selu_f(a);
            sb = selu_f(b);
            v += sqrtf(sa * sa + sb * sb);

            v += __shfl_xor_sync(0xffffffffu, v, 16);
            v += __shfl_xor_sync(0xffffffffu, v, 8);
            v += __shfl_xor_sync(0xffffffffu, v, 4);
            v += __shfl_xor_sync(0xffffffffu, v, 2);
            v += __shfl_xor_sync(0xffffffffu, v, 1);
            if (lane == 0) red[warp][cg * 8 + i] = v;
        }
    }

    __syncthreads();   // single barrier for the whole main phase
    if (tid < OF) {
        float s = 0.f;
        #pragma unroll
        for (int wz = 0; wz < 8; wz++) s += red[wz][tid];
        out[n * OF + tid] = s * (1.0f / 512.0f) * gsh[tid];
    }
}

extern "C" void kernel_launch(void* const* d_in, const int* in_sizes, int n_in,
                              void* d_out, int out_size) {
    const float* x      = (const float*)d_in[0];
    const float* weight = (const float*)d_in[1];
    const float* bias   = (const float*)d_in[2];
    const float* sproj  = (const float*)d_in[3];
    const float* sbias  = (const float*)d_in[4];
    float* out = (float*)d_out;
    fused_conv_selu_pool_gate<<<NIMG, THREADS>>>(x, weight, bias, sproj, sbias, out);
}

// round 6
// speedup vs baseline: 11.9800x; 1.2817x over previous
#include <cuda_runtime.h>
#include <math.h>

#define NIMG     1024
#define CIN      3
#define HH       32
#define WWID     32
#define OF       64
#define KPATCH   27
#define THREADS  256
#define XS_PITCH 36   // padded row pitch; rows 8B-aligned

#define SELU_SCALE   1.0507009873554805f
#define SELU_AS      1.7580993408473766f   // scale * alpha

typedef unsigned long long u64;

__constant__ float cw [KPATCH * OF];  // conv weights (27, 64) row-major
__constant__ float cb [OF];           // bias
__constant__ float csp[CIN * OF];     // scale_proj (3, 64)
__constant__ float csb[OF];           // scale_bias

__device__ __forceinline__ u64 dup2(float v) {
    u64 r;
    asm("mov.b64 %0, {%1, %1};" : "=l"(r) : "f"(v));
    return r;
}
__device__ __forceinline__ void unpack2(u64 v, float& a, float& b) {
    asm("mov.b64 {%0, %1}, %2;" : "=f"(a), "=f"(b) : "l"(v));
}
// Blackwell packed dual-FMA: 2 fp32 FMAs per instruction.
__device__ __forceinline__ void fma2(u64& acc, u64 x, u64 w) {
    asm("fma.rn.f32x2 %0, %1, %2, %0;" : "+l"(acc) : "l"(x), "l"(w));
}

// SELU; negative branch on MUFU pipe via __expf.
__device__ __forceinline__ float selu_f(float v) {
    float e   = __expf(v);
    float neg = fmaf(e, SELU_AS, -SELU_AS);
    return v > 0.0f ? SELU_SCALE * v : neg;
}

__global__ void __launch_bounds__(THREADS, 3) fused_conv_selu_pool_gate(
    const float* __restrict__ x,      // (1024, 3, 32, 32)
    float* __restrict__ out)          // (1024, 64)
{
    __shared__ __align__(16) float xs[CIN][34][XS_PITCH]; // image w/ halo
    __shared__ float gsh[OF];                             // gate
    __shared__ float red[8][OF];                          // per-warp partials
    __shared__ float csum_sh[8][CIN];                     // per-warp channel sums

    const int n    = blockIdx.x;
    const int tid  = threadIdx.x;
    const int lane = tid & 31;
    const int warp = tid >> 5;
    const float* xn = x + (size_t)n * (CIN * HH * WWID);

    // ---- stage image with zero halo; channel sums on the fly ----
    float cs0 = 0.f, cs1 = 0.f, cs2 = 0.f;
    for (int i = tid; i < CIN * 34 * 34; i += THREADS) {
        int c  = i / (34 * 34);
        int r  = i % (34 * 34);
        int hh = r / 34, ww = r % 34;
        float v = 0.f;
        if (hh >= 1 && hh <= 32 && ww >= 1 && ww <= 32) {
            v = xn[c * (HH * WWID) + (hh - 1) * WWID + (ww - 1)];
            if (c == 0)      cs0 += v;
            else if (c == 1) cs1 += v;
            else             cs2 += v;
        }
        xs[c][hh][ww] = v;
    }
    #pragma unroll
    for (int off = 16; off; off >>= 1) {
        cs0 += __shfl_xor_sync(0xffffffffu, cs0, off);
        cs1 += __shfl_xor_sync(0xffffffffu, cs1, off);
        cs2 += __shfl_xor_sync(0xffffffffu, cs2, off);
    }
    if (lane == 0) {
        csum_sh[warp][0] = cs0;
        csum_sh[warp][1] = cs1;
        csum_sh[warp][2] = cs2;
    }
    __syncthreads();

    // ---- gate: sigmoid(mean(x) @ scale_proj + scale_bias) ----
    if (tid < OF) {
        float s0 = 0.f, s1 = 0.f, s2 = 0.f;
        #pragma unroll
        for (int wz = 0; wz < 8; wz++) {
            s0 += csum_sh[wz][0];
            s1 += csum_sh[wz][1];
            s2 += csum_sh[wz][2];
        }
        const float inv = 1.0f / (HH * WWID);
        float z = s0 * inv * csp[0 * OF + tid]
                + s1 * inv * csp[1 * OF + tid]
                + s2 * inv * csp[2 * OF + tid]
                + csb[tid];
        gsh[tid] = 1.0f / (1.0f + __expf(-z));
    }
    __syncthreads();

    // Pair A covers output pixels (hA, w0), (hA, w0+1); pair B at hA+16.
    const int hA = tid >> 4;           // 0..15
    const int w0 = (tid & 15) << 1;    // 0..30
    const float* rowA0 = &xs[0][hA][w0];
    const float* rowB0 = rowA0 + 16 * XS_PITCH;

    // ---- main: conv + SELU + L2-pool(pairs along W) + spatial sum ----
    // Channels-in-lane: acc[px][j] lanes = channels (cg*8+2j, cg*8+2j+1).
    #pragma unroll 1
    for (int cg = 0; cg < 8; cg++) {
        u64 acc0[4], acc1[4], acc2[4], acc3[4];   // px0=A0, px1=A1, px2=B0, px3=B1
        {
            const ulonglong2* cbp = (const ulonglong2*)&cb[cg * 8];
            ulonglong2 q0 = cbp[0], q1 = cbp[1];
            acc0[0] = q0.x; acc0[1] = q0.y; acc0[2] = q1.x; acc0[3] = q1.y;
            #pragma unroll
            for (int j = 0; j < 4; j++) { acc1[j] = acc0[j]; acc2[j] = acc0[j]; acc3[j] = acc0[j]; }
        }

        const float* rA = rowA0;
        const float* rB = rowB0;
        const float* wrow = cw + cg * 8;     // advance 3*64 floats per body

        #pragma unroll 1
        for (int c = 0; c < 3; c++) {
            #pragma unroll 1
            for (int dy = 0; dy < 3; dy++) {
                float2 fa0 = *(const float2*)(rA);       // x[w0], x[w0+1]
                float2 fa1 = *(const float2*)(rA + 2);   // x[w0+2], x[w0+3]
                float2 fb0 = *(const float2*)(rB);
                float2 fb1 = *(const float2*)(rB + 2);
                u64 xA[4], xB[4];
                xA[0] = dup2(fa0.x); xA[1] = dup2(fa0.y);
                xA[2] = dup2(fa1.x); xA[3] = dup2(fa1.y);
                xB[0] = dup2(fb0.x); xB[1] = dup2(fb0.y);
                xB[2] = dup2(fb1.x); xB[3] = dup2(fb1.y);

                #pragma unroll
                for (int dx = 0; dx < 3; dx++) {
                    const ulonglong2* wp = (const ulonglong2*)(wrow + dx * OF);
                    ulonglong2 w01 = wp[0];   // channels 2j=0,1 pairs (const port)
                    ulonglong2 w23 = wp[1];
                    fma2(acc0[0], xA[dx],     w01.x);
                    fma2(acc0[1], xA[dx],     w01.y);
                    fma2(acc0[2], xA[dx],     w23.x);
                    fma2(acc0[3], xA[dx],     w23.y);
                    fma2(acc1[0], xA[dx + 1], w01.x);
                    fma2(acc1[1], xA[dx + 1], w01.y);
                    fma2(acc1[2], xA[dx + 1], w23.x);
                    fma2(acc1[3], xA[dx + 1], w23.y);
                    fma2(acc2[0], xB[dx],     w01.x);
                    fma2(acc2[1], xB[dx],     w01.y);
                    fma2(acc2[2], xB[dx],     w23.x);
                    fma2(acc2[3], xB[dx],     w23.y);
                    fma2(acc3[0], xB[dx + 1], w01.x);
                    fma2(acc3[1], xB[dx + 1], w01.y);
                    fma2(acc3[2], xB[dx + 1], w23.x);
                    fma2(acc3[3], xB[dx + 1], w23.y);
                }
                rA += XS_PITCH;
                rB += XS_PITCH;
                wrow += 3 * OF;
            }
            rA += (34 - 3) * XS_PITCH;   // next channel plane
            rB += (34 - 3) * XS_PITCH;
        }

        // SELU + pair-L2 + warp reduce. Channel pair stays packed through the pool.
        #pragma unroll
        for (int j = 0; j < 4; j++) {
            float a0l, a0h, a1l, a1h, b0l, b0h, b1l, b1h;
            unpack2(acc0[j], a0l, a0h);
            unpack2(acc1[j], a1l, a1h);
            unpack2(acc2[j], b0l, b0h);
            unpack2(acc3[j], b1l, b1h);
            a0l = selu_f(a0l); a0h = selu_f(a0h);
            a1l = selu_f(a1l); a1h = selu_f(a1h);
            b0l = selu_f(b0l); b0h = selu_f(b0h);
            b1l = selu_f(b1l); b1h = selu_f(b1h);
            float vl = sqrtf(fmaf(a1l, a1l, a0l * a0l)) + sqrtf(fmaf(b1l, b1l, b0l * b0l));
            float vh = sqrtf(fmaf(a1h, a1h, a0h * a0h)) + sqrtf(fmaf(b1h, b1h, b0h * b0h));
            #pragma unroll
            for (int off = 16; off; off >>= 1) {
                vl += __shfl_xor_sync(0xffffffffu, vl, off);
                vh += __shfl_xor_sync(0xffffffffu, vh, off);
            }
            if (lane == 0) {
                red[warp][cg * 8 + 2 * j]     = vl;
                red[warp][cg * 8 + 2 * j + 1] = vh;
            }
        }
    }

    __syncthreads();   // single barrier for the whole main phase
    if (tid < OF) {
        float s = 0.f;
        #pragma unroll
        for (int wz = 0; wz < 8; wz++) s += red[wz][tid];
        out[n * OF + tid] = s * (1.0f / 512.0f) * gsh[tid];
    }
}

extern "C" void kernel_launch(void* const* d_in, const int* in_sizes, int n_in,
                              void* d_out, int out_size) {
    const float* x      = (const float*)d_in[0];
    const float* weight = (const float*)d_in[1];
    const float* bias   = (const float*)d_in[2];
    const float* sproj  = (const float*)d_in[3];
    const float* sbias  = (const float*)d_in[4];
    float* out = (float*)d_out;

    cudaMemcpyToSymbolAsync(cw,  weight, KPATCH * OF * sizeof(float), 0, cudaMemcpyDeviceToDevice, 0);
    cudaMemcpyToSymbolAsync(cb,  bias,   OF * sizeof(float),          0, cudaMemcpyDeviceToDevice, 0);
    cudaMemcpyToSymbolAsync(csp, sproj,  CIN * OF * sizeof(float),    0, cudaMemcpyDeviceToDevice, 0);
    cudaMemcpyToSymbolAsync(csb, sbias,  OF * sizeof(float),          0, cudaMemcpyDeviceToDevice, 0);

    fused_conv_selu_pool_gate<<<NIMG, THREADS>>>(x, out);
}